// round 7
// baseline (speedup 1.0000x reference)
#include <cuda_runtime.h>

#define W_ 256
#define H_ 256
#define HW_ 65536
#define B_ 4
#define C_ 256
#define R_ 32
#define K_ 6

// 32 MB scratch for conf0 (B,R,H,W) — __device__ global (no allocation).
__device__ float g_conf0[B_ * R_ * HW_];
// f32 sin/cos of the 32 ray angles via libdevice sinf/cosf.
__device__ float g_sin[R_];
__device__ float g_cos[R_];

__constant__ float c_ef[5] = {0.2f, 0.4f, 0.6f, 0.8f, 1.0f};

// ---- packed f32x2 helpers (sm_103a) ----
__device__ __forceinline__ unsigned long long pack2(float lo, float hi)
{
    unsigned long long r;
    asm("mov.b64 %0, {%1, %2};" : "=l"(r) : "f"(lo), "f"(hi));
    return r;
}
__device__ __forceinline__ void unpack2(unsigned long long v, float& lo, float& hi)
{
    asm("mov.b64 {%0, %1}, %2;" : "=f"(lo), "=f"(hi) : "l"(v));
}
__device__ __forceinline__ void fma2(unsigned long long& d,
                                     unsigned long long a,
                                     unsigned long long b)
{
    asm("fma.rn.f32x2 %0, %1, %2, %0;" : "+l"(d) : "l"(a), "l"(b));
}

// Kernel 1: conf0[b,r,h,w] = sum_c features[b,c,h,w] * w0[r,c]
// 4 pixels/thread, 32 rays, packed f32x2 FMA. Weights duplicated as (w,w)
// pairs in dynamic SMEM, layout [r][c] so LDS.128 covers two channels.
__global__ __launch_bounds__(256) void conf0_kernel(
    const float* __restrict__ features,
    const float* __restrict__ w0)
{
    extern __shared__ float2 w0d[];  // [r][c] -> (w, w), 32*256*8 = 64 KB

    // trig table init (block 0 only) — identical libdevice ops as before
    if (blockIdx.x == 0 && threadIdx.x < R_) {
        int r = threadIdx.x;
        float ang = __fmul_rn(__fdiv_rn((float)r, 32.0f), 6.28318530717958647692f);
        g_sin[r] = sinf(ang);
        g_cos[r] = cosf(ang);
    }

    for (int i = threadIdx.x; i < R_ * C_; i += blockDim.x) {
        float v = w0[i];             // w0 is (R, C) row-major: i = r*256 + c
        w0d[i] = make_float2(v, v);
    }
    __syncthreads();

    int gp4 = (blockIdx.x * blockDim.x + threadIdx.x) * 4;  // first of 4 pixels
    int b   = gp4 >> 16;
    int pix = gp4 & (HW_ - 1);

    const float* fbase = features + (size_t)b * C_ * HW_ + pix;

    unsigned long long acc01[R_], acc23[R_];
    const unsigned long long z2 = pack2(0.0f, 0.0f);
#pragma unroll
    for (int r = 0; r < R_; r++) { acc01[r] = z2; acc23[r] = z2; }

#pragma unroll 2
    for (int c = 0; c < C_; c += 2) {
        float4 fa = *(const float4*)(fbase + (size_t)c * HW_);
        float4 fb = *(const float4*)(fbase + (size_t)(c + 1) * HW_);
        unsigned long long fa01 = pack2(fa.x, fa.y);
        unsigned long long fa23 = pack2(fa.z, fa.w);
        unsigned long long fb01 = pack2(fb.x, fb.y);
        unsigned long long fb23 = pack2(fb.z, fb.w);

#pragma unroll
        for (int r = 0; r < R_; r++) {
            // 16B load: (w[r][c],w[r][c]) , (w[r][c+1],w[r][c+1])
            ulonglong2 wv = *(const ulonglong2*)&w0d[r * C_ + c];
            fma2(acc01[r], fa01, wv.x);   // channel c   (order preserved per pixel)
            fma2(acc23[r], fa23, wv.x);
            fma2(acc01[r], fb01, wv.y);   // channel c+1
            fma2(acc23[r], fb23, wv.y);
        }
    }

    float* obase = g_conf0 + (size_t)b * R_ * HW_ + pix;
#pragma unroll
    for (int r = 0; r < R_; r++) {
        float4 o;
        unpack2(acc01[r], o.x, o.y);
        unpack2(acc23[r], o.z, o.w);
        *(float4*)(obase + (size_t)r * HW_) = o;
    }
}

// Kernel 2: fused erosion sampling + 6x6 matvec + bias + softmax + weighted sum + ReLU
// (numerics frozen — identical to the passing round-6 kernel)
__global__ __launch_bounds__(256) void refine_kernel(
    const float* __restrict__ sd,       // stardist (B,R,H,W)
    const float* __restrict__ w1,       // (K,K)
    const float* __restrict__ b1,       // (K,)
    float* __restrict__ ray_out,        // (B,R,H,W)
    float* __restrict__ conf_out)       // (B,K,R,H,W)
{
    __shared__ float w1s[K_ * K_];
    __shared__ float b1s[K_];
    if (threadIdx.x < K_ * K_) w1s[threadIdx.x] = w1[threadIdx.x];
    if (threadIdx.x < K_)      b1s[threadIdx.x] = b1[threadIdx.x];
    __syncthreads();

    int t = blockIdx.x * blockDim.x + threadIdx.x;
    int w = t & (W_ - 1);
    int h = (t >> 8) & (H_ - 1);
    int r = (t >> 16) & (R_ - 1);

    float s  = sd[t];
    float c0 = g_conf0[t];

    float sn = g_sin[r];
    float cs = g_cos[r];

    int plane = t & ~(HW_ - 1);
    const float* plane_s = sd + plane;
    const float* plane_c = g_conf0 + plane;

    float rays[K_], confs[K_];
    rays[0]  = s;
    confs[0] = c0;

    const float wf = (float)w;
    const float hf = (float)h;
    const float INV255 = 1.0f / 255.0f;  // XLA: x/255 -> x * fl(1/255)

#pragma unroll
    for (int e = 0; e < 5; e++) {
        float ef   = c_ef[e];
        float base = __fmul_rn(__fadd_rn(s, -1.0f), ef);
        float gx   = __fadd_rn(wf, __fmul_rn(cs, base));
        float gy   = __fadd_rn(hf, __fmul_rn(sn, base));
        float nx   = __fadd_rn(__fmul_rn(__fmul_rn(gx, INV255), 2.0f), -1.0f);
        float ny   = __fadd_rn(__fmul_rn(__fmul_rn(gy, INV255), 2.0f), -1.0f);
        float ixf  = __fmul_rn(__fadd_rn(__fmul_rn(__fadd_rn(nx, 1.0f), 256.0f), -1.0f), 0.5f);
        float iyf  = __fmul_rn(__fadd_rn(__fmul_rn(__fadd_rn(ny, 1.0f), 256.0f), -1.0f), 0.5f);
        float ixr  = rintf(ixf);
        float iyr  = rintf(iyf);
        bool valid = (ixr >= 0.0f) && (ixr < 256.0f) && (iyr >= 0.0f) && (iyr < 256.0f);
        int ix = min(max((int)ixr, 0), W_ - 1);
        int iy = min(max((int)iyr, 0), H_ - 1);
        int gi = iy * W_ + ix;
        float ss = valid ? plane_s[gi] : 0.0f;
        float cc = valid ? plane_c[gi] : 0.0f;
        rays[e + 1]  = __fadd_rn(ss, base);
        confs[e + 1] = cc;
    }

    float z[K_];
    float m = -3.0e38f;
#pragma unroll
    for (int j = 0; j < K_; j++) {
        float zz = 0.0f;
#pragma unroll
        for (int k = 0; k < K_; k++)
            zz = fmaf(w1s[j * K_ + k], confs[k], zz);
        zz = __fadd_rn(zz, b1s[j]);
        z[j] = zz;
        m = fmaxf(m, zz);
    }
    float sum = 0.0f;
#pragma unroll
    for (int j = 0; j < K_; j++) {
        z[j] = expf(__fadd_rn(z[j], -m));
        sum = __fadd_rn(sum, z[j]);
    }

    int hw = t & (HW_ - 1);
    size_t out_base = ((size_t)((t >> 21) * K_ * R_ + r)) * HW_ + hw;

    float acc = 0.0f;
#pragma unroll
    for (int j = 0; j < K_; j++) {
        float cf = __fdiv_rn(z[j], sum);
        acc = __fadd_rn(acc, __fmul_rn(rays[j], cf));
        conf_out[out_base + (size_t)(j * R_) * HW_] = cf;
    }
    ray_out[t] = fmaxf(acc, 0.0f);
}

extern "C" void kernel_launch(void* const* d_in, const int* in_sizes, int n_in,
                              void* d_out, int out_size)
{
    const float* sd       = (const float*)d_in[0];  // stardist_map (B,R,H,W)
    const float* features = (const float*)d_in[1];  // (B,C,H,W)
    const float* w0       = (const float*)d_in[2];  // (R,C)
    const float* w1       = (const float*)d_in[3];  // (K,K)
    const float* b1       = (const float*)d_in[4];  // (K,)

    float* out      = (float*)d_out;
    float* ray_out  = out;                              // (B,R,H,W)
    float* conf_out = out + (size_t)B_ * R_ * HW_;      // (B,K,R,H,W)

    const int SMEM_BYTES = R_ * C_ * (int)sizeof(float2);  // 64 KB
    static int configured = 0;
    if (!configured) {
        cudaFuncSetAttribute(conf0_kernel,
                             cudaFuncAttributeMaxDynamicSharedMemorySize, SMEM_BYTES);
        configured = 1;
    }

    conf0_kernel<<<(B_ * HW_) / (256 * 4), 256, SMEM_BYTES>>>(features, w0);
    refine_kernel<<<(B_ * R_ * HW_) / 256, 256>>>(sd, w1, b1, ray_out, conf_out);
}

// round 8
// speedup vs baseline: 1.0690x; 1.0690x over previous
#include <cuda_runtime.h>

#define W_ 256
#define H_ 256
#define HW_ 65536
#define B_ 4
#define C_ 256
#define R_ 32
#define K_ 6

// 32 MB scratch for conf0 (B,R,H,W) — __device__ global (no allocation).
__device__ float g_conf0[B_ * R_ * HW_];
__device__ float g_sin[R_];
__device__ float g_cos[R_];

__constant__ float c_ef[5] = {0.2f, 0.4f, 0.6f, 0.8f, 1.0f};

// ---- packed f32x2 helpers (sm_103a) ----
__device__ __forceinline__ unsigned long long pack2(float lo, float hi)
{
    unsigned long long r;
    asm("mov.b64 %0, {%1, %2};" : "=l"(r) : "f"(lo), "f"(hi));
    return r;
}
__device__ __forceinline__ void unpack2(unsigned long long v, float& lo, float& hi)
{
    asm("mov.b64 {%0, %1}, %2;" : "=f"(lo), "=f"(hi) : "l"(v));
}
__device__ __forceinline__ void fma2(unsigned long long& d,
                                     unsigned long long a,
                                     unsigned long long b)
{
    asm("fma.rn.f32x2 %0, %1, %2, %0;" : "+l"(d) : "l"(a), "l"(b));
}

// Kernel 1: conf0[b,r,h,w] = sum_c features[b,c,h,w] * w0[r,c]
// 1 pixel/thread. f32x2 packed over RAY PAIRS: weights [c][r] in SMEM are
// naturally adjacent pairs (no duplication), features duplicated per-register.
// Accumulation order over c identical to the scalar version (bit-exact).
__global__ __launch_bounds__(256) void conf0_kernel(
    const float* __restrict__ features,
    const float* __restrict__ w0)
{
    __shared__ float w0s[C_ * R_];  // [c][r], 32 KB

    // trig table init (block 0 only)
    if (blockIdx.x == 0 && threadIdx.x < R_) {
        int r = threadIdx.x;
        float ang = __fmul_rn(__fdiv_rn((float)r, 32.0f), 6.28318530717958647692f);
        g_sin[r] = sinf(ang);
        g_cos[r] = cosf(ang);
    }

    for (int i = threadIdx.x; i < R_ * C_; i += blockDim.x) {
        int r = i & (R_ - 1);   // i = c*32 + r
        int c = i >> 5;
        w0s[i] = w0[r * C_ + c];
    }
    __syncthreads();

    int gp  = blockIdx.x * blockDim.x + threadIdx.x;  // pixel among B*HW
    int b   = gp >> 16;
    int pix = gp & (HW_ - 1);

    const float* fbase = features + (size_t)b * C_ * HW_ + pix;

    unsigned long long acc[16];  // ray pairs (0,1),(2,3),...,(30,31)
    const unsigned long long z2 = pack2(0.0f, 0.0f);
#pragma unroll
    for (int q = 0; q < 16; q++) acc[q] = z2;

#pragma unroll 4
    for (int c = 0; c < C_; c++) {
        float f = __ldg(fbase + (size_t)c * HW_);
        unsigned long long ff = pack2(f, f);
        const ulonglong2* wp = (const ulonglong2*)&w0s[c * R_];
#pragma unroll
        for (int q = 0; q < 8; q++) {
            ulonglong2 wv = wp[q];      // LDS.128: rays 4q..4q+3 (broadcast)
            fma2(acc[2 * q],     ff, wv.x);
            fma2(acc[2 * q + 1], ff, wv.y);
        }
    }

    float* obase = g_conf0 + (size_t)b * R_ * HW_ + pix;
#pragma unroll
    for (int q = 0; q < 16; q++) {
        float lo, hi;
        unpack2(acc[q], lo, hi);
        obase[(size_t)(2 * q)     * HW_] = lo;
        obase[(size_t)(2 * q + 1) * HW_] = hi;
    }
}

// Kernel 2: fused erosion sampling + 6x6 matvec + bias + softmax + weighted
// sum + ReLU. 2 adjacent pixels per thread (same b, r, h; w even).
// Index chain numerics FROZEN (separate IEEE ops, reciprocal-const multiply).
__global__ __launch_bounds__(256) void refine_kernel(
    const float* __restrict__ sd,       // stardist (B,R,H,W)
    const float* __restrict__ w1,       // (K,K)
    const float* __restrict__ b1,       // (K,)
    float* __restrict__ ray_out,        // (B,R,H,W)
    float* __restrict__ conf_out)       // (B,K,R,H,W)
{
    __shared__ float w1s[K_ * K_];
    __shared__ float b1s[K_];
    if (threadIdx.x < K_ * K_) w1s[threadIdx.x] = w1[threadIdx.x];
    if (threadIdx.x < K_)      b1s[threadIdx.x] = b1[threadIdx.x];
    __syncthreads();

    int t2 = (blockIdx.x * blockDim.x + threadIdx.x) * 2;
    int w  = t2 & (W_ - 1);          // even
    int h  = (t2 >> 8) & (H_ - 1);
    int r  = (t2 >> 16) & (R_ - 1);
    int b  = t2 >> 21;

    float2 sv  = *(const float2*)(sd + t2);
    float2 c0v = *(const float2*)(g_conf0 + t2);

    float sn = g_sin[r];
    float cs = g_cos[r];

    int plane = t2 & ~(HW_ - 1);
    const float* plane_s = sd + plane;
    const float* plane_c = g_conf0 + plane;

    const float hf = (float)h;
    const float INV255 = 1.0f / 255.0f;   // XLA: x/255 -> x * fl(1/255)

    float rays[2][K_], confs[2][K_];
    rays[0][0] = sv.x;  confs[0][0] = c0v.x;
    rays[1][0] = sv.y;  confs[1][0] = c0v.y;

#pragma unroll
    for (int px = 0; px < 2; px++) {
        float s  = px ? sv.y : sv.x;
        float wf = (float)(w + px);
#pragma unroll
        for (int e = 0; e < 5; e++) {
            float ef   = c_ef[e];
            float base = __fmul_rn(__fadd_rn(s, -1.0f), ef);
            float gx   = __fadd_rn(wf, __fmul_rn(cs, base));
            float gy   = __fadd_rn(hf, __fmul_rn(sn, base));
            float nx   = __fadd_rn(__fmul_rn(__fmul_rn(gx, INV255), 2.0f), -1.0f);
            float ny   = __fadd_rn(__fmul_rn(__fmul_rn(gy, INV255), 2.0f), -1.0f);
            float ixf  = __fmul_rn(__fadd_rn(__fmul_rn(__fadd_rn(nx, 1.0f), 256.0f), -1.0f), 0.5f);
            float iyf  = __fmul_rn(__fadd_rn(__fmul_rn(__fadd_rn(ny, 1.0f), 256.0f), -1.0f), 0.5f);
            float ixr  = rintf(ixf);   // round half to even == jnp.round
            float iyr  = rintf(iyf);
            bool valid = (ixr >= 0.0f) && (ixr < 256.0f) && (iyr >= 0.0f) && (iyr < 256.0f);
            int ix = min(max((int)ixr, 0), W_ - 1);
            int iy = min(max((int)iyr, 0), H_ - 1);
            int gi = iy * W_ + ix;
            float ss = valid ? plane_s[gi] : 0.0f;
            float cc = valid ? plane_c[gi] : 0.0f;
            rays[px][e + 1]  = __fadd_rn(ss, base);
            confs[px][e + 1] = cc;
        }
    }

    int hw = t2 & (HW_ - 1);
    size_t out_base = ((size_t)(b * K_ * R_ + r)) * HW_ + hw;

    float2 rr;
    float racc[2];
    float2 cfv[K_];

#pragma unroll
    for (int px = 0; px < 2; px++) {
        float z[K_];
        float m = -3.0e38f;
#pragma unroll
        for (int j = 0; j < K_; j++) {
            float zz = 0.0f;
#pragma unroll
            for (int k = 0; k < K_; k++)
                zz = fmaf(w1s[j * K_ + k], confs[px][k], zz);
            zz = __fadd_rn(zz, b1s[j]);
            z[j] = zz;
            m = fmaxf(m, zz);
        }
        float sum = 0.0f;
#pragma unroll
        for (int j = 0; j < K_; j++) {
            z[j] = __expf(__fadd_rn(z[j], -m));   // MUFU-based exp (values only)
            sum = __fadd_rn(sum, z[j]);
        }
        float inv = __fdiv_rn(1.0f, sum);

        float acc = 0.0f;
#pragma unroll
        for (int j = 0; j < K_; j++) {
            float cf = __fmul_rn(z[j], inv);
            acc = __fadd_rn(acc, __fmul_rn(rays[px][j], cf));
            if (px == 0) cfv[j].x = cf; else cfv[j].y = cf;
        }
        racc[px] = fmaxf(acc, 0.0f);
    }

#pragma unroll
    for (int j = 0; j < K_; j++)
        *(float2*)(conf_out + out_base + (size_t)(j * R_) * HW_) = cfv[j];

    rr.x = racc[0];
    rr.y = racc[1];
    *(float2*)(ray_out + t2) = rr;
}

extern "C" void kernel_launch(void* const* d_in, const int* in_sizes, int n_in,
                              void* d_out, int out_size)
{
    const float* sd       = (const float*)d_in[0];  // stardist_map (B,R,H,W)
    const float* features = (const float*)d_in[1];  // (B,C,H,W)
    const float* w0       = (const float*)d_in[2];  // (R,C)
    const float* w1       = (const float*)d_in[3];  // (K,K)
    const float* b1       = (const float*)d_in[4];  // (K,)

    float* out      = (float*)d_out;
    float* ray_out  = out;                              // (B,R,H,W)
    float* conf_out = out + (size_t)B_ * R_ * HW_;      // (B,K,R,H,W)

    conf0_kernel<<<(B_ * HW_) / 256, 256>>>(features, w0);
    refine_kernel<<<(B_ * R_ * HW_) / (256 * 2), 256>>>(sd, w1, b1, ray_out, conf_out);
}

// round 9
// speedup vs baseline: 1.6006x; 1.4973x over previous
#include <cuda_runtime.h>

#define W_ 256
#define H_ 256
#define HW_ 65536
#define B_ 4
#define C_ 256
#define R_ 32
#define K_ 6

// 32 MB scratch for conf0 (B,R,H,W) — __device__ global (no allocation).
__device__ float g_conf0[B_ * R_ * HW_];
__device__ float g_sin[R_];
__device__ float g_cos[R_];

__constant__ float c_ef[5] = {0.2f, 0.4f, 0.6f, 0.8f, 1.0f};

// TF32 rounding (round-to-nearest-A), as used by tensor-core TF32 paths.
__device__ __forceinline__ float tf32r(float x)
{
    unsigned u;
    asm("cvt.rna.tf32.f32 %0, %1;" : "=r"(u) : "f"(x));
    return __uint_as_float(u);
}

#define FS_STRIDE 264  // %32 == 8 -> B-fragment LDS bank = (8*tg + grp)%32, conflict-free

// Kernel 1: conf0 = w0(32x256) @ features(256xHW) per batch, TF32 MMA, fp32 accum.
// CTA: 128 threads (4 warps), tile = 32 rays x 256 pixels, K looped in 8 tiles of 32.
__global__ __launch_bounds__(128) void conf0_mma_kernel(
    const float* __restrict__ features,
    const float* __restrict__ w0)
{
    __shared__ float fs[32 * FS_STRIDE];  // one 32-channel x 256-pixel tile (tf32-rounded)

    // trig table init (block 0) — frozen numerics
    if (blockIdx.x == 0 && threadIdx.x < R_) {
        int r = threadIdx.x;
        float ang = __fmul_rn(__fdiv_rn((float)r, 32.0f), 6.28318530717958647692f);
        g_sin[r] = sinf(ang);
        g_cos[r] = cosf(ang);
    }

    int tid  = threadIdx.x;
    int wi   = tid >> 5;          // warp 0..3 -> pixel slice of 64
    int lane = tid & 31;
    int grp  = lane >> 2;         // 0..7
    int tg   = lane & 3;          // 0..3

    int gp   = blockIdx.x << 8;   // 256 pixels per CTA
    int b    = gp >> 16;
    int pix0 = gp & (HW_ - 1);

    const float* fbase = features + (size_t)b * C_ * HW_ + pix0;

    float c[2][8][4];
#pragma unroll
    for (int mt = 0; mt < 2; mt++)
#pragma unroll
        for (int nt = 0; nt < 8; nt++)
#pragma unroll
            for (int i = 0; i < 4; i++) c[mt][nt][i] = 0.0f;

    for (int kt = 0; kt < 8; kt++) {
        __syncthreads();  // protect previous tile's reads
        // stage 32 channels x 256 pixels, tf32-rounded, coalesced float4
        for (int i = tid; i < 2048; i += 128) {
            int row = i >> 6;
            int c4  = (i & 63) << 2;
            float4 v = *(const float4*)(fbase + (size_t)(kt * 32 + row) * HW_ + c4);
            float4 t;
            t.x = tf32r(v.x); t.y = tf32r(v.y); t.z = tf32r(v.z); t.w = tf32r(v.w);
            *(float4*)&fs[row * FS_STRIDE + c4] = t;
        }
        __syncthreads();

        const float* w0k = w0 + kt * 32;
#pragma unroll
        for (int ks = 0; ks < 4; ks++) {
            // A fragments from global w0 (32 KB, L1/L2-resident)
            unsigned a[2][4];
#pragma unroll
            for (int mt = 0; mt < 2; mt++) {
                int ray0 = mt * 16 + grp;
                int ch   = ks * 8 + tg;
                a[mt][0] = __float_as_uint(tf32r(__ldg(w0k + ray0 * C_ + ch)));
                a[mt][1] = __float_as_uint(tf32r(__ldg(w0k + (ray0 + 8) * C_ + ch)));
                a[mt][2] = __float_as_uint(tf32r(__ldg(w0k + ray0 * C_ + ch + 4)));
                a[mt][3] = __float_as_uint(tf32r(__ldg(w0k + (ray0 + 8) * C_ + ch + 4)));
            }
#pragma unroll
            for (int nt = 0; nt < 8; nt++) {
                int col = wi * 64 + nt * 8 + grp;
                unsigned b0 = __float_as_uint(fs[(ks * 8 + tg) * FS_STRIDE + col]);
                unsigned b1 = __float_as_uint(fs[(ks * 8 + tg + 4) * FS_STRIDE + col]);
#pragma unroll
                for (int mt = 0; mt < 2; mt++) {
                    asm volatile(
                        "mma.sync.aligned.m16n8k8.row.col.f32.tf32.tf32.f32 "
                        "{%0,%1,%2,%3}, {%4,%5,%6,%7}, {%8,%9}, {%0,%1,%2,%3};"
                        : "+f"(c[mt][nt][0]), "+f"(c[mt][nt][1]),
                          "+f"(c[mt][nt][2]), "+f"(c[mt][nt][3])
                        : "r"(a[mt][0]), "r"(a[mt][1]), "r"(a[mt][2]), "r"(a[mt][3]),
                          "r"(b0), "r"(b1));
                }
            }
        }
    }

    // epilogue: c0/c1 -> (row=grp, cols 2tg,2tg+1); c2/c3 -> row grp+8
    float* obase = g_conf0 + (size_t)b * R_ * HW_ + pix0;
#pragma unroll
    for (int mt = 0; mt < 2; mt++) {
#pragma unroll
        for (int nt = 0; nt < 8; nt++) {
            int col  = wi * 64 + nt * 8 + tg * 2;
            int ray0 = mt * 16 + grp;
            *(float2*)(obase + (size_t)ray0 * HW_ + col) =
                make_float2(c[mt][nt][0], c[mt][nt][1]);
            *(float2*)(obase + (size_t)(ray0 + 8) * HW_ + col) =
                make_float2(c[mt][nt][2], c[mt][nt][3]);
        }
    }
}

// Kernel 2: fused erosion sampling + 6x6 matvec + bias + softmax + weighted sum
// + ReLU. 1 pixel/thread (round-7 shape: regs~36, occ~70%).
// Index chain numerics FROZEN. expf -> __expf, 6 divides -> 1 divide + muls.
__global__ __launch_bounds__(256) void refine_kernel(
    const float* __restrict__ sd,       // stardist (B,R,H,W)
    const float* __restrict__ w1,       // (K,K)
    const float* __restrict__ b1,       // (K,)
    float* __restrict__ ray_out,        // (B,R,H,W)
    float* __restrict__ conf_out)       // (B,K,R,H,W)
{
    __shared__ float w1s[K_ * K_];
    __shared__ float b1s[K_];
    if (threadIdx.x < K_ * K_) w1s[threadIdx.x] = w1[threadIdx.x];
    if (threadIdx.x < K_)      b1s[threadIdx.x] = b1[threadIdx.x];
    __syncthreads();

    int t = blockIdx.x * blockDim.x + threadIdx.x;
    int w = t & (W_ - 1);
    int h = (t >> 8) & (H_ - 1);
    int r = (t >> 16) & (R_ - 1);

    float s  = sd[t];
    float c0 = g_conf0[t];

    float sn = g_sin[r];
    float cs = g_cos[r];

    int plane = t & ~(HW_ - 1);
    const float* plane_s = sd + plane;
    const float* plane_c = g_conf0 + plane;

    float rays[K_], confs[K_];
    rays[0]  = s;
    confs[0] = c0;

    const float wf = (float)w;
    const float hf = (float)h;
    const float INV255 = 1.0f / 255.0f;  // XLA: x/255 -> x * fl(1/255)

#pragma unroll
    for (int e = 0; e < 5; e++) {
        float ef   = c_ef[e];
        float base = __fmul_rn(__fadd_rn(s, -1.0f), ef);
        float gx   = __fadd_rn(wf, __fmul_rn(cs, base));
        float gy   = __fadd_rn(hf, __fmul_rn(sn, base));
        float nx   = __fadd_rn(__fmul_rn(__fmul_rn(gx, INV255), 2.0f), -1.0f);
        float ny   = __fadd_rn(__fmul_rn(__fmul_rn(gy, INV255), 2.0f), -1.0f);
        float ixf  = __fmul_rn(__fadd_rn(__fmul_rn(__fadd_rn(nx, 1.0f), 256.0f), -1.0f), 0.5f);
        float iyf  = __fmul_rn(__fadd_rn(__fmul_rn(__fadd_rn(ny, 1.0f), 256.0f), -1.0f), 0.5f);
        float ixr  = rintf(ixf);  // round half to even == jnp.round
        float iyr  = rintf(iyf);
        bool valid = (ixr >= 0.0f) && (ixr < 256.0f) && (iyr >= 0.0f) && (iyr < 256.0f);
        int ix = min(max((int)ixr, 0), W_ - 1);
        int iy = min(max((int)iyr, 0), H_ - 1);
        int gi = iy * W_ + ix;
        float ss = valid ? plane_s[gi] : 0.0f;
        float cc = valid ? plane_c[gi] : 0.0f;
        rays[e + 1]  = __fadd_rn(ss, base);
        confs[e + 1] = cc;
    }

    float z[K_];
    float m = -3.0e38f;
#pragma unroll
    for (int j = 0; j < K_; j++) {
        float zz = 0.0f;
#pragma unroll
        for (int k = 0; k < K_; k++)
            zz = fmaf(w1s[j * K_ + k], confs[k], zz);
        zz = __fadd_rn(zz, b1s[j]);
        z[j] = zz;
        m = fmaxf(m, zz);
    }
    float sum = 0.0f;
#pragma unroll
    for (int j = 0; j < K_; j++) {
        z[j] = __expf(__fadd_rn(z[j], -m));   // MUFU-based exp (values only)
        sum = __fadd_rn(sum, z[j]);
    }
    float inv = __fdiv_rn(1.0f, sum);

    int hw = t & (HW_ - 1);
    size_t out_base = ((size_t)((t >> 21) * K_ * R_ + r)) * HW_ + hw;

    float acc = 0.0f;
#pragma unroll
    for (int j = 0; j < K_; j++) {
        float cf = __fmul_rn(z[j], inv);
        acc = __fadd_rn(acc, __fmul_rn(rays[j], cf));
        conf_out[out_base + (size_t)(j * R_) * HW_] = cf;
    }
    ray_out[t] = fmaxf(acc, 0.0f);
}

extern "C" void kernel_launch(void* const* d_in, const int* in_sizes, int n_in,
                              void* d_out, int out_size)
{
    const float* sd       = (const float*)d_in[0];  // stardist_map (B,R,H,W)
    const float* features = (const float*)d_in[1];  // (B,C,H,W)
    const float* w0       = (const float*)d_in[2];  // (R,C)
    const float* w1       = (const float*)d_in[3];  // (K,K)
    const float* b1       = (const float*)d_in[4];  // (K,)

    float* out      = (float*)d_out;
    float* ray_out  = out;                              // (B,R,H,W)
    float* conf_out = out + (size_t)B_ * R_ * HW_;      // (B,K,R,H,W)

    conf0_mma_kernel<<<(B_ * HW_) / 256, 128>>>(features, w0);
    refine_kernel<<<(B_ * R_ * HW_) / 256, 256>>>(sd, w1, b1, ray_out, conf_out);
}

// round 10
// speedup vs baseline: 1.6755x; 1.0468x over previous
#include <cuda_runtime.h>

#define W_ 256
#define H_ 256
#define HW_ 65536
#define B_ 4
#define C_ 256
#define R_ 32
#define K_ 6

// 32 MB scratch for conf0 (B,R,H,W) — __device__ global (no allocation).
__device__ float g_conf0[B_ * R_ * HW_];
__device__ float g_sin[R_];
__device__ float g_cos[R_];

__constant__ float c_ef[5] = {0.2f, 0.4f, 0.6f, 0.8f, 1.0f};

// TF32 rounding (round-to-nearest-A), as used by tensor-core TF32 paths.
__device__ __forceinline__ float tf32r(float x)
{
    unsigned u;
    asm("cvt.rna.tf32.f32 %0, %1;" : "=r"(u) : "f"(x));
    return __uint_as_float(u);
}

// Kernel 1: conf0 = w0(32x256) @ features(256xHW) per batch, TF32 MMA, fp32 accum.
// No feature staging / no k-loop barriers: each warp streams a 64-px strip with
// sector-perfect direct LDGs (4 channel rows x 8 consecutive px per LDG.32).
// w0 tf32-rounded once into padded SMEM (conflict-free A-fragment LDS).
__global__ __launch_bounds__(256) void conf0_mma_kernel(
    const float* __restrict__ features,
    const float* __restrict__ w0)
{
    __shared__ float w0s[R_][257];   // pad 257: A-frag LDS conflict-free

    // trig table init (block 0) — frozen numerics
    if (blockIdx.x == 0 && threadIdx.x < R_) {
        int r = threadIdx.x;
        float ang = __fmul_rn(__fdiv_rn((float)r, 32.0f), 6.28318530717958647692f);
        g_sin[r] = sinf(ang);
        g_cos[r] = cosf(ang);
    }

    int tid  = threadIdx.x;
    int wi   = tid >> 5;          // warp 0..7 -> 64-pixel slice
    int lane = tid & 31;
    int grp  = lane >> 2;         // 0..7
    int tg   = lane & 3;          // 0..3

    // stage w0 (tf32-rounded) once
    for (int i = tid; i < R_ * C_; i += 256)
        w0s[i >> 8][i & 255] = tf32r(w0[i]);
    __syncthreads();

    int gp   = blockIdx.x * 512;            // 512 px per CTA (8 warps x 64)
    int b    = gp >> 16;
    int pix0 = (gp & (HW_ - 1)) + wi * 64;  // this warp's pixel base

    const float* fb = features + (size_t)b * C_ * HW_ + pix0;

    float c[2][8][4];
#pragma unroll
    for (int mt = 0; mt < 2; mt++)
#pragma unroll
        for (int nt = 0; nt < 8; nt++)
#pragma unroll
            for (int i = 0; i < 4; i++) c[mt][nt][i] = 0.0f;

    for (int kt = 0; kt < 8; kt++) {
#pragma unroll
        for (int ks = 0; ks < 4; ks++) {
            int ch = kt * 32 + ks * 8 + tg;

            unsigned a[2][4];
#pragma unroll
            for (int mt = 0; mt < 2; mt++) {
                int ray0 = mt * 16 + grp;
                a[mt][0] = __float_as_uint(w0s[ray0][ch]);
                a[mt][1] = __float_as_uint(w0s[ray0 + 8][ch]);
                a[mt][2] = __float_as_uint(w0s[ray0][ch + 4]);
                a[mt][3] = __float_as_uint(w0s[ray0 + 8][ch + 4]);
            }

            const float* frow0 = fb + (size_t)ch * HW_;
            const float* frow1 = fb + (size_t)(ch + 4) * HW_;

#pragma unroll
            for (int nt = 0; nt < 8; nt++) {
                int col = nt * 8 + grp;
                unsigned b0 = __float_as_uint(tf32r(__ldg(frow0 + col)));
                unsigned b1 = __float_as_uint(tf32r(__ldg(frow1 + col)));
#pragma unroll
                for (int mt = 0; mt < 2; mt++) {
                    asm volatile(
                        "mma.sync.aligned.m16n8k8.row.col.f32.tf32.tf32.f32 "
                        "{%0,%1,%2,%3}, {%4,%5,%6,%7}, {%8,%9}, {%0,%1,%2,%3};"
                        : "+f"(c[mt][nt][0]), "+f"(c[mt][nt][1]),
                          "+f"(c[mt][nt][2]), "+f"(c[mt][nt][3])
                        : "r"(a[mt][0]), "r"(a[mt][1]), "r"(a[mt][2]), "r"(a[mt][3]),
                          "r"(b0), "r"(b1));
                }
            }
        }
    }

    float* obase = g_conf0 + (size_t)b * R_ * HW_ + pix0;
#pragma unroll
    for (int mt = 0; mt < 2; mt++) {
#pragma unroll
        for (int nt = 0; nt < 8; nt++) {
            int col  = nt * 8 + tg * 2;
            int ray0 = mt * 16 + grp;
            *(float2*)(obase + (size_t)ray0 * HW_ + col) =
                make_float2(c[mt][nt][0], c[mt][nt][1]);
            *(float2*)(obase + (size_t)(ray0 + 8) * HW_ + col) =
                make_float2(c[mt][nt][2], c[mt][nt][3]);
        }
    }
}

// Kernel 2: fused erosion sampling + 6x6 matvec + bias + softmax + weighted sum
// + ReLU. 1 pixel/thread. Index-chain fp numerics FROZEN (bit-identical);
// integer epilogue slimmed: cvt.rni.s32 + unsigned range checks + index select.
__global__ __launch_bounds__(256) void refine_kernel(
    const float* __restrict__ sd,       // stardist (B,R,H,W)
    const float* __restrict__ w1,       // (K,K)
    const float* __restrict__ b1,       // (K,)
    float* __restrict__ ray_out,        // (B,R,H,W)
    float* __restrict__ conf_out)       // (B,K,R,H,W)
{
    __shared__ float w1s[K_ * K_];
    __shared__ float b1s[K_];
    if (threadIdx.x < K_ * K_) w1s[threadIdx.x] = w1[threadIdx.x];
    if (threadIdx.x < K_)      b1s[threadIdx.x] = b1[threadIdx.x];
    __syncthreads();

    int t = blockIdx.x * blockDim.x + threadIdx.x;
    int w = t & (W_ - 1);
    int h = (t >> 8) & (H_ - 1);
    int r = (t >> 16) & (R_ - 1);

    float s  = sd[t];
    float c0 = g_conf0[t];

    float sn = g_sin[r];
    float cs = g_cos[r];

    int plane = t & ~(HW_ - 1);
    const float* plane_s = sd + plane;
    const float* plane_c = g_conf0 + plane;

    float rays[K_], confs[K_];
    rays[0]  = s;
    confs[0] = c0;

    const float wf = (float)w;
    const float hf = (float)h;
    const float INV255 = 1.0f / 255.0f;  // XLA: x/255 -> x * fl(1/255)

#pragma unroll
    for (int e = 0; e < 5; e++) {
        float ef   = c_ef[e];
        float base = __fmul_rn(__fadd_rn(s, -1.0f), ef);
        float gx   = __fadd_rn(wf, __fmul_rn(cs, base));
        float gy   = __fadd_rn(hf, __fmul_rn(sn, base));
        float nx   = __fadd_rn(__fmul_rn(__fmul_rn(gx, INV255), 2.0f), -1.0f);
        float ny   = __fadd_rn(__fmul_rn(__fmul_rn(gy, INV255), 2.0f), -1.0f);
        float ixf  = __fmul_rn(__fadd_rn(__fmul_rn(__fadd_rn(nx, 1.0f), 256.0f), -1.0f), 0.5f);
        float iyf  = __fmul_rn(__fadd_rn(__fmul_rn(__fadd_rn(ny, 1.0f), 256.0f), -1.0f), 0.5f);
        int ix0 = __float2int_rn(ixf);   // cvt.rni.s32: round half to even, == rintf+trunc
        int iy0 = __float2int_rn(iyf);
        bool valid = ((unsigned)ix0 < 256u) && ((unsigned)iy0 < 256u);
        int gi = valid ? (iy0 * W_ + ix0) : 0;
        float ss = plane_s[gi];
        float cc = plane_c[gi];
        ss = valid ? ss : 0.0f;
        cc = valid ? cc : 0.0f;
        rays[e + 1]  = __fadd_rn(ss, base);
        confs[e + 1] = cc;
    }

    float z[K_];
    float m = -3.0e38f;
#pragma unroll
    for (int j = 0; j < K_; j++) {
        float zz = 0.0f;
#pragma unroll
        for (int k = 0; k < K_; k++)
            zz = fmaf(w1s[j * K_ + k], confs[k], zz);
        zz = __fadd_rn(zz, b1s[j]);
        z[j] = zz;
        m = fmaxf(m, zz);
    }
    float sum = 0.0f;
#pragma unroll
    for (int j = 0; j < K_; j++) {
        z[j] = __expf(__fadd_rn(z[j], -m));   // MUFU-based exp (values only)
        sum = __fadd_rn(sum, z[j]);
    }
    float inv = __fdiv_rn(1.0f, sum);

    int hw = t & (HW_ - 1);
    size_t out_base = ((size_t)((t >> 21) * K_ * R_ + r)) * HW_ + hw;

    float acc = 0.0f;
#pragma unroll
    for (int j = 0; j < K_; j++) {
        float cf = __fmul_rn(z[j], inv);
        acc = __fadd_rn(acc, __fmul_rn(rays[j], cf));
        conf_out[out_base + (size_t)(j * R_) * HW_] = cf;
    }
    ray_out[t] = fmaxf(acc, 0.0f);
}

extern "C" void kernel_launch(void* const* d_in, const int* in_sizes, int n_in,
                              void* d_out, int out_size)
{
    const float* sd       = (const float*)d_in[0];  // stardist_map (B,R,H,W)
    const float* features = (const float*)d_in[1];  // (B,C,H,W)
    const float* w0       = (const float*)d_in[2];  // (R,C)
    const float* w1       = (const float*)d_in[3];  // (K,K)
    const float* b1       = (const float*)d_in[4];  // (K,)

    float* out      = (float*)d_out;
    float* ray_out  = out;                              // (B,R,H,W)
    float* conf_out = out + (size_t)B_ * R_ * HW_;      // (B,K,R,H,W)

    conf0_mma_kernel<<<(B_ * HW_) / 512, 256>>>(features, w0);
    refine_kernel<<<(B_ * R_ * HW_) / 256, 256>>>(sd, w1, b1, ray_out, conf_out);
}

// round 11
// speedup vs baseline: 1.7401x; 1.0386x over previous
#include <cuda_runtime.h>

#define W_ 256
#define H_ 256
#define HW_ 65536
#define B_ 4
#define C_ 256
#define R_ 32
#define K_ 6

__device__ float g_conf0[B_ * R_ * HW_];
__device__ float g_sin[R_];
__device__ float g_cos[R_];

__constant__ float c_ef[5] = {0.2f, 0.4f, 0.6f, 0.8f, 1.0f};

__device__ __forceinline__ float tf32r(float x)
{
    unsigned u;
    asm("cvt.rna.tf32.f32 %0, %1;" : "=r"(u) : "f"(x));
    return __uint_as_float(u);
}

// ---- packed f32x2 helpers (two independent IEEE-RN ops per instruction) ----
__device__ __forceinline__ unsigned long long pack2(float lo, float hi)
{
    unsigned long long r;
    asm("mov.b64 %0, {%1, %2};" : "=l"(r) : "f"(lo), "f"(hi));
    return r;
}
__device__ __forceinline__ void unpack2(unsigned long long v, float& lo, float& hi)
{
    asm("mov.b64 {%0, %1}, %2;" : "=f"(lo), "=f"(hi) : "l"(v));
}
__device__ __forceinline__ unsigned long long mul2(unsigned long long a, unsigned long long b)
{
    unsigned long long d;
    asm("mul.rn.f32x2 %0, %1, %2;" : "=l"(d) : "l"(a), "l"(b));
    return d;
}
__device__ __forceinline__ unsigned long long add2(unsigned long long a, unsigned long long b)
{
    unsigned long long d;
    asm("add.rn.f32x2 %0, %1, %2;" : "=l"(d) : "l"(a), "l"(b));
    return d;
}
__device__ __forceinline__ void fma2(unsigned long long& d,
                                     unsigned long long a,
                                     unsigned long long b)
{
    asm("fma.rn.f32x2 %0, %1, %2, %0;" : "+l"(d) : "l"(a), "l"(b));
}

// Kernel 1: conf0 = w0(32x256) @ features(256xHW), TF32 MMA, fp32 accum.
// Barrier-free direct B loads + register double-buffer: step k+1's 16 LDGs
// issue before step k's MMAs -> loads continuously overlap tensor work.
__global__ __launch_bounds__(256) void conf0_mma_kernel(
    const float* __restrict__ features,
    const float* __restrict__ w0)
{
    __shared__ float w0s[R_][257];

    if (blockIdx.x == 0 && threadIdx.x < R_) {
        int r = threadIdx.x;
        float ang = __fmul_rn(__fdiv_rn((float)r, 32.0f), 6.28318530717958647692f);
        g_sin[r] = sinf(ang);
        g_cos[r] = cosf(ang);
    }

    int tid  = threadIdx.x;
    int wi   = tid >> 5;
    int lane = tid & 31;
    int grp  = lane >> 2;
    int tg   = lane & 3;

    for (int i = tid; i < R_ * C_; i += 256)
        w0s[i >> 8][i & 255] = tf32r(w0[i]);
    __syncthreads();

    int gp   = blockIdx.x * 512;
    int b    = gp >> 16;
    int pix0 = (gp & (HW_ - 1)) + wi * 64;

    const float* fb = features + (size_t)b * C_ * HW_ + pix0;

    float c[2][8][4];
#pragma unroll
    for (int mt = 0; mt < 2; mt++)
#pragma unroll
        for (int nt = 0; nt < 8; nt++)
#pragma unroll
            for (int i = 0; i < 4; i++) c[mt][nt][i] = 0.0f;

    unsigned bu[2][16];   // [buf][b0 x8, b1 x8]

    // prefetch step 0
    {
        const float* f0 = fb + (size_t)tg * HW_;
        const float* f1 = fb + (size_t)(tg + 4) * HW_;
#pragma unroll
        for (int nt = 0; nt < 8; nt++) {
            bu[0][nt]     = __float_as_uint(tf32r(__ldg(f0 + nt * 8 + grp)));
            bu[0][8 + nt] = __float_as_uint(tf32r(__ldg(f1 + nt * 8 + grp)));
        }
    }

#pragma unroll 4
    for (int k8 = 0; k8 < 32; k8++) {
        int cur = k8 & 1;
        // prefetch next step's B fragments (overlaps this step's MMAs)
        if (k8 < 31) {
            int chn = (k8 + 1) * 8 + tg;
            const float* f0 = fb + (size_t)chn * HW_;
            const float* f1 = fb + (size_t)(chn + 4) * HW_;
#pragma unroll
            for (int nt = 0; nt < 8; nt++) {
                bu[cur ^ 1][nt]     = __float_as_uint(tf32r(__ldg(f0 + nt * 8 + grp)));
                bu[cur ^ 1][8 + nt] = __float_as_uint(tf32r(__ldg(f1 + nt * 8 + grp)));
            }
        }

        int ch = k8 * 8 + tg;
        unsigned a[2][4];
#pragma unroll
        for (int mt = 0; mt < 2; mt++) {
            int ray0 = mt * 16 + grp;
            a[mt][0] = __float_as_uint(w0s[ray0][ch]);
            a[mt][1] = __float_as_uint(w0s[ray0 + 8][ch]);
            a[mt][2] = __float_as_uint(w0s[ray0][ch + 4]);
            a[mt][3] = __float_as_uint(w0s[ray0 + 8][ch + 4]);
        }

#pragma unroll
        for (int nt = 0; nt < 8; nt++) {
#pragma unroll
            for (int mt = 0; mt < 2; mt++) {
                asm volatile(
                    "mma.sync.aligned.m16n8k8.row.col.f32.tf32.tf32.f32 "
                    "{%0,%1,%2,%3}, {%4,%5,%6,%7}, {%8,%9}, {%0,%1,%2,%3};"
                    : "+f"(c[mt][nt][0]), "+f"(c[mt][nt][1]),
                      "+f"(c[mt][nt][2]), "+f"(c[mt][nt][3])
                    : "r"(a[mt][0]), "r"(a[mt][1]), "r"(a[mt][2]), "r"(a[mt][3]),
                      "r"(bu[cur][nt]), "r"(bu[cur][8 + nt]));
            }
        }
    }

    float* obase = g_conf0 + (size_t)b * R_ * HW_ + pix0;
#pragma unroll
    for (int mt = 0; mt < 2; mt++) {
#pragma unroll
        for (int nt = 0; nt < 8; nt++) {
            int col  = nt * 8 + tg * 2;
            int ray0 = mt * 16 + grp;
            *(float2*)(obase + (size_t)ray0 * HW_ + col) =
                make_float2(c[mt][nt][0], c[mt][nt][1]);
            *(float2*)(obase + (size_t)(ray0 + 8) * HW_ + col) =
                make_float2(c[mt][nt][2], c[mt][nt][3]);
        }
    }
}

// Kernel 2: fused refine. 1 px/thread. Index chain packed into f32x2
// (two independent IEEE-RN lanes -> bit-identical to the scalar chain).
__global__ __launch_bounds__(256) void refine_kernel(
    const float* __restrict__ sd,
    const float* __restrict__ w1,
    const float* __restrict__ b1,
    float* __restrict__ ray_out,
    float* __restrict__ conf_out)
{
    __shared__ float2 w1p[K_ * 3];   // [k][jpair]: (w1[2p][k], w1[2p+1][k])
    __shared__ float b1s[K_];
    if (threadIdx.x < K_ * 3) {
        int k = threadIdx.x / 3, p = threadIdx.x % 3;
        w1p[k * 3 + p] = make_float2(w1[(2 * p) * K_ + k], w1[(2 * p + 1) * K_ + k]);
    }
    if (threadIdx.x < K_) b1s[threadIdx.x] = b1[threadIdx.x];
    __syncthreads();

    int t = blockIdx.x * blockDim.x + threadIdx.x;
    int w = t & (W_ - 1);
    int h = (t >> 8) & (H_ - 1);
    int r = (t >> 16) & (R_ - 1);

    float s  = sd[t];
    float c0 = g_conf0[t];

    unsigned long long cssn = pack2(g_cos[r], g_sin[r]);
    unsigned long long wh   = pack2((float)w, (float)h);

    int plane = t & ~(HW_ - 1);
    const float* plane_s = sd + plane;
    const float* plane_c = g_conf0 + plane;

    float rays[K_], confs[K_];
    rays[0]  = s;
    confs[0] = c0;

    const float INV255 = 1.0f / 255.0f;
    const unsigned long long inv255_2 = pack2(INV255, INV255);
    const unsigned long long two2  = pack2(2.0f, 2.0f);
    const unsigned long long neg12 = pack2(-1.0f, -1.0f);
    const unsigned long long one2  = pack2(1.0f, 1.0f);
    const unsigned long long c2562 = pack2(256.0f, 256.0f);
    const unsigned long long half2 = pack2(0.5f, 0.5f);

#pragma unroll
    for (int e = 0; e < 5; e++) {
        float ef   = c_ef[e];
        float base = __fmul_rn(__fadd_rn(s, -1.0f), ef);
        unsigned long long base2 = pack2(base, base);
        // g = wh + cssn*base ; n = (g*inv255)*2 - 1 ; i = ((n+1)*256 - 1)*0.5
        unsigned long long g2 = add2(wh, mul2(cssn, base2));
        unsigned long long n2 = add2(mul2(mul2(g2, inv255_2), two2), neg12);
        unsigned long long i2 = mul2(add2(mul2(add2(n2, one2), c2562), neg12), half2);
        float ixf, iyf;
        unpack2(i2, ixf, iyf);
        int ix0 = __float2int_rn(ixf);   // cvt.rni: round half to even
        int iy0 = __float2int_rn(iyf);
        bool valid = ((unsigned)ix0 < 256u) && ((unsigned)iy0 < 256u);
        int gi = valid ? (iy0 * W_ + ix0) : 0;
        float ss = plane_s[gi];
        float cc = plane_c[gi];
        ss = valid ? ss : 0.0f;
        cc = valid ? cc : 0.0f;
        rays[e + 1]  = __fadd_rn(ss, base);
        confs[e + 1] = cc;
    }

    // z[jpair] via packed fma2: per-j accumulation order over k unchanged
    unsigned long long zp[3];
    zp[0] = zp[1] = zp[2] = pack2(0.0f, 0.0f);
#pragma unroll
    for (int k = 0; k < K_; k++) {
        unsigned long long ck = pack2(confs[k], confs[k]);
#pragma unroll
        for (int p = 0; p < 3; p++) {
            float2 wv = w1p[k * 3 + p];
            fma2(zp[p], ck, pack2(wv.x, wv.y));
        }
    }
    float z[K_];
#pragma unroll
    for (int p = 0; p < 3; p++) {
        float lo, hi;
        unpack2(zp[p], lo, hi);
        z[2 * p]     = __fadd_rn(lo, b1s[2 * p]);
        z[2 * p + 1] = __fadd_rn(hi, b1s[2 * p + 1]);
    }
    float m = -3.0e38f;
#pragma unroll
    for (int j = 0; j < K_; j++) m = fmaxf(m, z[j]);
    float sum = 0.0f;
#pragma unroll
    for (int j = 0; j < K_; j++) {
        z[j] = __expf(__fadd_rn(z[j], -m));
        sum = __fadd_rn(sum, z[j]);
    }
    float inv = __fdiv_rn(1.0f, sum);

    int hw = t & (HW_ - 1);
    size_t out_base = ((size_t)((t >> 21) * K_ * R_ + r)) * HW_ + hw;

    float acc = 0.0f;
#pragma unroll
    for (int j = 0; j < K_; j++) {
        float cf = __fmul_rn(z[j], inv);
        acc = __fadd_rn(acc, __fmul_rn(rays[j], cf));
        conf_out[out_base + (size_t)(j * R_) * HW_] = cf;
    }
    ray_out[t] = fmaxf(acc, 0.0f);
}

extern "C" void kernel_launch(void* const* d_in, const int* in_sizes, int n_in,
                              void* d_out, int out_size)
{
    const float* sd       = (const float*)d_in[0];
    const float* features = (const float*)d_in[1];
    const float* w0       = (const float*)d_in[2];
    const float* w1       = (const float*)d_in[3];
    const float* b1       = (const float*)d_in[4];

    float* out      = (float*)d_out;
    float* ray_out  = out;
    float* conf_out = out + (size_t)B_ * R_ * HW_;

    conf0_mma_kernel<<<(B_ * HW_) / 512, 256>>>(features, w0);
    refine_kernel<<<(B_ * R_ * HW_) / 256, 256>>>(sd, w1, b1, ray_out, conf_out);
}

// round 12
// speedup vs baseline: 2.1779x; 1.2516x over previous
#include <cuda_runtime.h>

#define W_ 256
#define H_ 256
#define HW_ 65536
#define B_ 4
#define C_ 256
#define R_ 32
#define K_ 6

__device__ float g_conf0[B_ * R_ * HW_];
__device__ float g_sin[R_];
__device__ float g_cos[R_];

__constant__ float c_ef[5] = {0.2f, 0.4f, 0.6f, 0.8f, 1.0f};

__device__ __forceinline__ float tf32r(float x)
{
    unsigned u;
    asm("cvt.rna.tf32.f32 %0, %1;" : "=r"(u) : "f"(x));
    return __uint_as_float(u);
}

// ---- packed f32x2 helpers ----
__device__ __forceinline__ unsigned long long pack2(float lo, float hi)
{
    unsigned long long r;
    asm("mov.b64 %0, {%1, %2};" : "=l"(r) : "f"(lo), "f"(hi));
    return r;
}
__device__ __forceinline__ void unpack2(unsigned long long v, float& lo, float& hi)
{
    asm("mov.b64 {%0, %1}, %2;" : "=f"(lo), "=f"(hi) : "l"(v));
}
__device__ __forceinline__ unsigned long long mul2(unsigned long long a, unsigned long long b)
{
    unsigned long long d;
    asm("mul.rn.f32x2 %0, %1, %2;" : "=l"(d) : "l"(a), "l"(b));
    return d;
}
__device__ __forceinline__ unsigned long long add2(unsigned long long a, unsigned long long b)
{
    unsigned long long d;
    asm("add.rn.f32x2 %0, %1, %2;" : "=l"(d) : "l"(a), "l"(b));
    return d;
}
__device__ __forceinline__ void fma2(unsigned long long& d,
                                     unsigned long long a,
                                     unsigned long long b)
{
    asm("fma.rn.f32x2 %0, %1, %2, %0;" : "+l"(d) : "l"(a), "l"(b));
}

// ---- conf0: TF32 MMA with warp-private 4-stage cp.async pipeline ----
// SMEM layout (dynamic): [0, 32*257) = w0s ; then fs[4 stages][8 warps][8 rows][72]
#define W0S_FLOATS (R_ * 257)
#define FS_ROW     72                       // 64 px + 8 pad; conflict-free frag LDS
#define FS_WARP    (8 * FS_ROW)             // 576
#define FS_STAGE   (8 * FS_WARP)            // 4608
#define SMEM_FLOATS (W0S_FLOATS + 4 * FS_STAGE)

__global__ __launch_bounds__(256) void conf0_mma_kernel(
    const float* __restrict__ features,
    const float* __restrict__ w0)
{
    extern __shared__ float smem[];
    float* w0s = smem;                 // [r][257]
    float* fs  = smem + W0S_FLOATS;

    if (blockIdx.x == 0 && threadIdx.x < R_) {
        int r = threadIdx.x;
        float ang = __fmul_rn(__fdiv_rn((float)r, 32.0f), 6.28318530717958647692f);
        g_sin[r] = sinf(ang);
        g_cos[r] = cosf(ang);
    }

    int tid  = threadIdx.x;
    int wi   = tid >> 5;
    int lane = tid & 31;
    int grp  = lane >> 2;
    int tg   = lane & 3;

    for (int i = tid; i < R_ * C_; i += 256)
        w0s[(i >> 8) * 257 + (i & 255)] = tf32r(w0[i]);
    __syncthreads();

    int gp   = blockIdx.x * 512;
    int b    = gp >> 16;
    int pix0 = (gp & (HW_ - 1)) + wi * 64;       // this warp's pixel base

    const float* fb = features + (size_t)b * C_ * HW_ + pix0;

    // warp-private slice base (u32 smem address)
    unsigned fsw = (unsigned)__cvta_generic_to_shared(fs + wi * FS_WARP);

    float c[2][8][4];
#pragma unroll
    for (int mt = 0; mt < 2; mt++)
#pragma unroll
        for (int nt = 0; nt < 8; nt++)
#pragma unroll
            for (int i = 0; i < 4; i++) c[mt][nt][i] = 0.0f;

    // stage loader: 8 channels x 64 px, 4x cp.async.cg 16B per lane
#define LOAD_STAGE(st, ch0)                                                      \
    {                                                                            \
        _Pragma("unroll")                                                        \
        for (int i = 0; i < 4; i++) {                                            \
            int e   = lane + 32 * i;                                             \
            int row = e >> 4;                                                    \
            int f4  = e & 15;                                                    \
            const float* g = fb + (size_t)((ch0) + row) * HW_ + f4 * 4;          \
            unsigned s = fsw + (unsigned)(((st) * FS_STAGE + row * FS_ROW) * 4 + f4 * 16); \
            asm volatile("cp.async.cg.shared.global [%0], [%1], 16;"             \
                         :: "r"(s), "l"(g));                                     \
        }                                                                        \
    }

    // prologue: stages 0..2
#pragma unroll
    for (int st = 0; st < 3; st++) {
        LOAD_STAGE(st, st * 8);
        asm volatile("cp.async.commit_group;");
    }

#pragma unroll 4
    for (int k8 = 0; k8 < 32; k8++) {
        if (k8 + 3 < 32) LOAD_STAGE((k8 + 3) & 3, (k8 + 3) * 8);
        asm volatile("cp.async.commit_group;");   // empty group near tail keeps count uniform
        asm volatile("cp.async.wait_group 3;");
        __syncwarp();

        int cur = k8 & 3;
        const float* fcur = fs + wi * FS_WARP + cur * FS_STAGE;

        int ch = k8 * 8 + tg;
        unsigned a[2][4];
#pragma unroll
        for (int mt = 0; mt < 2; mt++) {
            int ray0 = mt * 16 + grp;
            a[mt][0] = __float_as_uint(w0s[ray0 * 257 + ch]);
            a[mt][1] = __float_as_uint(w0s[(ray0 + 8) * 257 + ch]);
            a[mt][2] = __float_as_uint(w0s[ray0 * 257 + ch + 4]);
            a[mt][3] = __float_as_uint(w0s[(ray0 + 8) * 257 + ch + 4]);
        }

#pragma unroll
        for (int nt = 0; nt < 8; nt++) {
            int col = nt * 8 + grp;
            unsigned b0 = __float_as_uint(tf32r(fcur[tg * FS_ROW + col]));
            unsigned b1 = __float_as_uint(tf32r(fcur[(tg + 4) * FS_ROW + col]));
#pragma unroll
            for (int mt = 0; mt < 2; mt++) {
                asm volatile(
                    "mma.sync.aligned.m16n8k8.row.col.f32.tf32.tf32.f32 "
                    "{%0,%1,%2,%3}, {%4,%5,%6,%7}, {%8,%9}, {%0,%1,%2,%3};"
                    : "+f"(c[mt][nt][0]), "+f"(c[mt][nt][1]),
                      "+f"(c[mt][nt][2]), "+f"(c[mt][nt][3])
                    : "r"(a[mt][0]), "r"(a[mt][1]), "r"(a[mt][2]), "r"(a[mt][3]),
                      "r"(b0), "r"(b1));
            }
        }
    }

    float* obase = g_conf0 + (size_t)b * R_ * HW_ + pix0;
#pragma unroll
    for (int mt = 0; mt < 2; mt++) {
#pragma unroll
        for (int nt = 0; nt < 8; nt++) {
            int col  = nt * 8 + tg * 2;
            int ray0 = mt * 16 + grp;
            *(float2*)(obase + (size_t)ray0 * HW_ + col) =
                make_float2(c[mt][nt][0], c[mt][nt][1]);
            *(float2*)(obase + (size_t)(ray0 + 8) * HW_ + col) =
                make_float2(c[mt][nt][2], c[mt][nt][3]);
        }
    }
}

// Kernel 2: fused refine (FROZEN — identical to round 11).
__global__ __launch_bounds__(256) void refine_kernel(
    const float* __restrict__ sd,
    const float* __restrict__ w1,
    const float* __restrict__ b1,
    float* __restrict__ ray_out,
    float* __restrict__ conf_out)
{
    __shared__ float2 w1p[K_ * 3];
    __shared__ float b1s[K_];
    if (threadIdx.x < K_ * 3) {
        int k = threadIdx.x / 3, p = threadIdx.x % 3;
        w1p[k * 3 + p] = make_float2(w1[(2 * p) * K_ + k], w1[(2 * p + 1) * K_ + k]);
    }
    if (threadIdx.x < K_) b1s[threadIdx.x] = b1[threadIdx.x];
    __syncthreads();

    int t = blockIdx.x * blockDim.x + threadIdx.x;
    int w = t & (W_ - 1);
    int h = (t >> 8) & (H_ - 1);
    int r = (t >> 16) & (R_ - 1);

    float s  = sd[t];
    float c0 = g_conf0[t];

    unsigned long long cssn = pack2(g_cos[r], g_sin[r]);
    unsigned long long wh   = pack2((float)w, (float)h);

    int plane = t & ~(HW_ - 1);
    const float* plane_s = sd + plane;
    const float* plane_c = g_conf0 + plane;

    float rays[K_], confs[K_];
    rays[0]  = s;
    confs[0] = c0;

    const float INV255 = 1.0f / 255.0f;
    const unsigned long long inv255_2 = pack2(INV255, INV255);
    const unsigned long long two2  = pack2(2.0f, 2.0f);
    const unsigned long long neg12 = pack2(-1.0f, -1.0f);
    const unsigned long long one2  = pack2(1.0f, 1.0f);
    const unsigned long long c2562 = pack2(256.0f, 256.0f);
    const unsigned long long half2 = pack2(0.5f, 0.5f);

#pragma unroll
    for (int e = 0; e < 5; e++) {
        float ef   = c_ef[e];
        float base = __fmul_rn(__fadd_rn(s, -1.0f), ef);
        unsigned long long base2 = pack2(base, base);
        unsigned long long g2 = add2(wh, mul2(cssn, base2));
        unsigned long long n2 = add2(mul2(mul2(g2, inv255_2), two2), neg12);
        unsigned long long i2 = mul2(add2(mul2(add2(n2, one2), c2562), neg12), half2);
        float ixf, iyf;
        unpack2(i2, ixf, iyf);
        int ix0 = __float2int_rn(ixf);
        int iy0 = __float2int_rn(iyf);
        bool valid = ((unsigned)ix0 < 256u) && ((unsigned)iy0 < 256u);
        int gi = valid ? (iy0 * W_ + ix0) : 0;
        float ss = plane_s[gi];
        float cc = plane_c[gi];
        ss = valid ? ss : 0.0f;
        cc = valid ? cc : 0.0f;
        rays[e + 1]  = __fadd_rn(ss, base);
        confs[e + 1] = cc;
    }

    unsigned long long zp[3];
    zp[0] = zp[1] = zp[2] = pack2(0.0f, 0.0f);
#pragma unroll
    for (int k = 0; k < K_; k++) {
        unsigned long long ck = pack2(confs[k], confs[k]);
#pragma unroll
        for (int p = 0; p < 3; p++) {
            float2 wv = w1p[k * 3 + p];
            fma2(zp[p], ck, pack2(wv.x, wv.y));
        }
    }
    float z[K_];
#pragma unroll
    for (int p = 0; p < 3; p++) {
        float lo, hi;
        unpack2(zp[p], lo, hi);
        z[2 * p]     = __fadd_rn(lo, b1s[2 * p]);
        z[2 * p + 1] = __fadd_rn(hi, b1s[2 * p + 1]);
    }
    float m = -3.0e38f;
#pragma unroll
    for (int j = 0; j < K_; j++) m = fmaxf(m, z[j]);
    float sum = 0.0f;
#pragma unroll
    for (int j = 0; j < K_; j++) {
        z[j] = __expf(__fadd_rn(z[j], -m));
        sum = __fadd_rn(sum, z[j]);
    }
    float inv = __fdiv_rn(1.0f, sum);

    int hw = t & (HW_ - 1);
    size_t out_base = ((size_t)((t >> 21) * K_ * R_ + r)) * HW_ + hw;

    float acc = 0.0f;
#pragma unroll
    for (int j = 0; j < K_; j++) {
        float cf = __fmul_rn(z[j], inv);
        acc = __fadd_rn(acc, __fmul_rn(rays[j], cf));
        conf_out[out_base + (size_t)(j * R_) * HW_] = cf;
    }
    ray_out[t] = fmaxf(acc, 0.0f);
}

extern "C" void kernel_launch(void* const* d_in, const int* in_sizes, int n_in,
                              void* d_out, int out_size)
{
    const float* sd       = (const float*)d_in[0];
    const float* features = (const float*)d_in[1];
    const float* w0       = (const float*)d_in[2];
    const float* w1       = (const float*)d_in[3];
    const float* b1       = (const float*)d_in[4];

    float* out      = (float*)d_out;
    float* ray_out  = out;
    float* conf_out = out + (size_t)B_ * R_ * HW_;

    const int SMEM_BYTES = SMEM_FLOATS * (int)sizeof(float);   // ~104 KB
    cudaFuncSetAttribute(conf0_mma_kernel,
                         cudaFuncAttributeMaxDynamicSharedMemorySize, SMEM_BYTES);

    conf0_mma_kernel<<<(B_ * HW_) / 512, 256, SMEM_BYTES>>>(features, w0);
    refine_kernel<<<(B_ * R_ * HW_) / 256, 256>>>(sd, w1, b1, ray_out, conf_out);
}